// round 1
// baseline (speedup 1.0000x reference)
#include <cuda_runtime.h>
#include <math.h>

#define BM 128
#define BN 128
#define BK 8
#define TM 8
#define TN 8
#define THREADS 256

#define BATCH   8192
#define UNITS   2048
#define IN_DIM  2048
#define G_LD    6144   // 3*UNITS

// Scratch (allocation-free: __device__ globals)
__device__ float g_G[(size_t)BATCH * G_LD];     // 192 MB: [xr+hr | xu+hu->u | xh]
__device__ float g_rh[(size_t)BATCH * UNITS];   // 64 MB: r * h

__device__ __forceinline__ float sigmoidf_(float x) {
    return 1.0f / (1.0f + __expf(-x));
}

// ---------------------------------------------------------------------------
// Classic SGEMM: C[M,N] (+)= A[M,K] @ B[K,N], row-major, all dims multiples of tile
// ---------------------------------------------------------------------------
__global__ void __launch_bounds__(THREADS)
sgemm_kernel(const float* __restrict__ A, int lda,
             const float* __restrict__ B, int ldb,
             float* __restrict__ C, int ldc,
             int K, int accumulate)
{
    __shared__ float As[BK][BM];
    __shared__ float Bs[BK][BN];

    const int tid = threadIdx.x;
    const int tx = tid & 15;          // 0..15  -> col group
    const int ty = tid >> 4;          // 0..15  -> row group
    const int m0 = blockIdx.y * BM;
    const int n0 = blockIdx.x * BN;

    const int aRow = tid >> 1;        // 0..127
    const int aCol = (tid & 1) * 4;   // 0 or 4
    const int bRow = tid >> 5;        // 0..7
    const int bCol = (tid & 31) * 4;  // 0..124

    const float* Aptr = A + (size_t)(m0 + aRow) * lda + aCol;
    const float* Bptr = B + (size_t)bRow * ldb + n0 + bCol;

    float acc[TM][TN];
#pragma unroll
    for (int i = 0; i < TM; i++)
#pragma unroll
        for (int j = 0; j < TN; j++) acc[i][j] = 0.0f;

    for (int k0 = 0; k0 < K; k0 += BK) {
        float4 av = *(const float4*)(Aptr + k0);
        As[aCol + 0][aRow] = av.x;
        As[aCol + 1][aRow] = av.y;
        As[aCol + 2][aRow] = av.z;
        As[aCol + 3][aRow] = av.w;
        float4 bv = *(const float4*)(Bptr + (size_t)k0 * ldb);
        *(float4*)&Bs[bRow][bCol] = bv;
        __syncthreads();

#pragma unroll
        for (int k = 0; k < BK; ++k) {
            float a[TM], b[TN];
#pragma unroll
            for (int i = 0; i < TM; i++) a[i] = As[k][ty * TM + i];
#pragma unroll
            for (int j = 0; j < TN; j++) b[j] = Bs[k][tx * TN + j];
#pragma unroll
            for (int i = 0; i < TM; i++)
#pragma unroll
                for (int j = 0; j < TN; j++)
                    acc[i][j] = fmaf(a[i], b[j], acc[i][j]);
        }
        __syncthreads();
    }

    // Write out (vectorized, optional accumulate)
#pragma unroll
    for (int i = 0; i < TM; i++) {
        const size_t row = (size_t)(m0 + ty * TM + i);
        float* cp = C + row * ldc + n0 + tx * TN;
#pragma unroll
        for (int j4 = 0; j4 < TN; j4 += 4) {
            float4 v = make_float4(acc[i][j4], acc[i][j4 + 1], acc[i][j4 + 2], acc[i][j4 + 3]);
            if (accumulate) {
                float4 o = *(float4*)(cp + j4);
                v.x += o.x; v.y += o.y; v.z += o.z; v.w += o.w;
            }
            *(float4*)(cp + j4) = v;
        }
    }
}

// ---------------------------------------------------------------------------
// Gates: r = sigmoid(G[:, :u] + b_r); u = sigmoid(G[:, u:2u] + b_u)
//        rh = r * h  -> g_rh;  store u back into G[:, u:2u]
// ---------------------------------------------------------------------------
__global__ void __launch_bounds__(256)
gates_kernel(const float* __restrict__ h, const float* __restrict__ bias,
             float* __restrict__ G, float* __restrict__ rh)
{
    const int idx4 = blockIdx.x * blockDim.x + threadIdx.x;   // 0 .. BATCH*UNITS/4
    const int row  = idx4 / (UNITS / 4);
    const int j    = (idx4 % (UNITS / 4)) * 4;

    const size_t gbase = (size_t)row * G_LD;
    float4 gr = *(const float4*)(G + gbase + j);
    float4 gu = *(const float4*)(G + gbase + UNITS + j);
    float4 br = *(const float4*)(bias + j);
    float4 bu = *(const float4*)(bias + UNITS + j);
    float4 hv = *(const float4*)(h + (size_t)row * UNITS + j);

    float4 r, u;
    r.x = sigmoidf_(gr.x + br.x); r.y = sigmoidf_(gr.y + br.y);
    r.z = sigmoidf_(gr.z + br.z); r.w = sigmoidf_(gr.w + br.w);
    u.x = sigmoidf_(gu.x + bu.x); u.y = sigmoidf_(gu.y + bu.y);
    u.z = sigmoidf_(gu.z + bu.z); u.w = sigmoidf_(gu.w + bu.w);

    float4 rh4;
    rh4.x = r.x * hv.x; rh4.y = r.y * hv.y; rh4.z = r.z * hv.z; rh4.w = r.w * hv.w;

    *(float4*)(rh + (size_t)row * UNITS + j) = rh4;
    *(float4*)(G + gbase + UNITS + j) = u;   // store u_t in place
}

// ---------------------------------------------------------------------------
// Final GEMM: ch = rh @ W_h[:, 2u:]  fused with
//   h_t = u*h + (1-u)*tanh(xh + ch + b_h)
// ---------------------------------------------------------------------------
__global__ void __launch_bounds__(THREADS)
sgemm_final_kernel(const float* __restrict__ A, int lda,       // rh
                   const float* __restrict__ B, int ldb,       // W_h + 2u (col offset applied)
                   const float* __restrict__ G,                // xh at col 2u, u at col u
                   const float* __restrict__ h,
                   const float* __restrict__ bias,
                   float* __restrict__ out, int K)
{
    __shared__ float As[BK][BM];
    __shared__ float Bs[BK][BN];

    const int tid = threadIdx.x;
    const int tx = tid & 15;
    const int ty = tid >> 4;
    const int m0 = blockIdx.y * BM;
    const int n0 = blockIdx.x * BN;

    const int aRow = tid >> 1;
    const int aCol = (tid & 1) * 4;
    const int bRow = tid >> 5;
    const int bCol = (tid & 31) * 4;

    const float* Aptr = A + (size_t)(m0 + aRow) * lda + aCol;
    const float* Bptr = B + (size_t)bRow * ldb + n0 + bCol;

    float acc[TM][TN];
#pragma unroll
    for (int i = 0; i < TM; i++)
#pragma unroll
        for (int j = 0; j < TN; j++) acc[i][j] = 0.0f;

    for (int k0 = 0; k0 < K; k0 += BK) {
        float4 av = *(const float4*)(Aptr + k0);
        As[aCol + 0][aRow] = av.x;
        As[aCol + 1][aRow] = av.y;
        As[aCol + 2][aRow] = av.z;
        As[aCol + 3][aRow] = av.w;
        float4 bv = *(const float4*)(Bptr + (size_t)k0 * ldb);
        *(float4*)&Bs[bRow][bCol] = bv;
        __syncthreads();

#pragma unroll
        for (int k = 0; k < BK; ++k) {
            float a[TM], b[TN];
#pragma unroll
            for (int i = 0; i < TM; i++) a[i] = As[k][ty * TM + i];
#pragma unroll
            for (int j = 0; j < TN; j++) b[j] = Bs[k][tx * TN + j];
#pragma unroll
            for (int i = 0; i < TM; i++)
#pragma unroll
                for (int j = 0; j < TN; j++)
                    acc[i][j] = fmaf(a[i], b[j], acc[i][j]);
        }
        __syncthreads();
    }

    // Fused GRU epilogue
#pragma unroll
    for (int i = 0; i < TM; i++) {
        const int row = m0 + ty * TM + i;
        const size_t gbase = (size_t)row * G_LD;
        const int col0 = n0 + tx * TN;
#pragma unroll
        for (int j = 0; j < TN; j++) {
            const int col = col0 + j;
            float xh = G[gbase + 2 * UNITS + col];
            float u  = G[gbase + UNITS + col];
            float hv = h[(size_t)row * UNITS + col];
            float bh = bias[2 * UNITS + col];
            float cand = tanhf(acc[i][j] + xh + bh);
            out[(size_t)row * UNITS + col] = u * hv + (1.0f - u) * cand;
        }
    }
}

// ---------------------------------------------------------------------------
extern "C" void kernel_launch(void* const* d_in, const int* in_sizes, int n_in,
                              void* d_out, int out_size)
{
    const float* x    = (const float*)d_in[0];   // [8192, 2048]
    const float* h    = (const float*)d_in[1];   // [8192, 2048]
    const float* Win  = (const float*)d_in[2];   // [2048, 6144]
    const float* Wh   = (const float*)d_in[3];   // [2048, 6144]
    const float* bias = (const float*)d_in[4];   // [6144]
    float* out = (float*)d_out;                  // [8192, 2048]

    float *G, *rh;
    cudaGetSymbolAddress((void**)&G, g_G);
    cudaGetSymbolAddress((void**)&rh, g_rh);

    dim3 blk(THREADS);

    // 1) G[:, :6144] = x @ W_in
    dim3 g1(3 * UNITS / BN, BATCH / BM);
    sgemm_kernel<<<g1, blk>>>(x, IN_DIM, Win, 3 * UNITS, G, G_LD, IN_DIM, 0);

    // 2) G[:, :4096] += h @ W_h[:, :4096]
    dim3 g2(2 * UNITS / BN, BATCH / BM);
    sgemm_kernel<<<g2, blk>>>(h, UNITS, Wh, 3 * UNITS, G, G_LD, UNITS, 1);

    // 3) gates: r, u, rh
    int n4 = BATCH * UNITS / 4;
    gates_kernel<<<n4 / 256, 256>>>(h, bias, G, rh);

    // 4) final GEMM + fused epilogue
    dim3 g3(UNITS / BN, BATCH / BM);
    sgemm_final_kernel<<<g3, blk>>>(rh, UNITS, Wh + 2 * UNITS, 3 * UNITS,
                                    G, h, bias, out, UNITS);
}

// round 3
// speedup vs baseline: 2.8313x; 2.8313x over previous
#include <cuda_runtime.h>
#include <math.h>
#include <stdint.h>

#define BATCH 8192
#define U2    2048
#define GL    6144

#define BM 128
#define BN 128
#define BK 32
#define STAGES 3
#define THREADS 256

#define A_STAGE_BYTES (BM * BK * 4)            // 16384, SW128-swizzled rows of 128B
#define BSTRIDE 132                             // floats per B smem row (pad 4)
#define B_STAGE_BYTES (BK * BSTRIDE * 4)        // 16896
#define STAGE_BYTES (A_STAGE_BYTES + B_STAGE_BYTES)
#define SMEM_ALLOC (STAGES * STAGE_BYTES + 256)

// tf32-rounded operand copies + intermediates (allocation-free scratch)
__device__ float g_xR [(size_t)BATCH * U2];
__device__ float g_hR [(size_t)BATCH * U2];
__device__ float g_WinR[(size_t)U2 * GL];
__device__ float g_WhR [(size_t)U2 * GL];
__device__ float g_rh [(size_t)BATCH * U2];   // tf32-rounded r*h
__device__ float g_U  [(size_t)BATCH * U2];   // update gate
__device__ float g_XH [(size_t)BATCH * U2];   // x@Win[:,2u:] raw

// ---------------- helpers ----------------
__device__ __forceinline__ uint32_t smem_u32(const void* p) {
    uint32_t a;
    asm("{ .reg .u64 t; cvta.to.shared.u64 t, %1; cvt.u32.u64 %0, t; }" : "=r"(a) : "l"(p));
    return a;
}
__device__ __forceinline__ void cp16(uint32_t dst, const void* src) {
    asm volatile("cp.async.cg.shared.global [%0], [%1], 16;" :: "r"(dst), "l"(src));
}
__device__ __forceinline__ void cp_commit() {
    asm volatile("cp.async.commit_group;" ::: "memory");
}
template<int N> __device__ __forceinline__ void cp_wait() {
    asm volatile("cp.async.wait_group %0;" :: "n"(N) : "memory");
}
__device__ __forceinline__ void ldsm_x4(uint32_t* r, uint32_t addr) {
    asm volatile("ldmatrix.sync.aligned.m8n8.x4.shared.b16 {%0,%1,%2,%3}, [%4];"
                 : "=r"(r[0]), "=r"(r[1]), "=r"(r[2]), "=r"(r[3]) : "r"(addr));
}
__device__ __forceinline__ uint32_t lds32(uint32_t addr) {
    uint32_t v;
    asm volatile("ld.shared.b32 %0, [%1];" : "=r"(v) : "r"(addr));
    return v;
}
__device__ __forceinline__ void mma_tf32(float* d, const uint32_t* a, const uint32_t* b) {
    asm volatile(
        "mma.sync.aligned.m16n8k8.row.col.f32.tf32.tf32.f32 "
        "{%0,%1,%2,%3}, {%4,%5,%6,%7}, {%8,%9}, {%0,%1,%2,%3};"
        : "+f"(d[0]), "+f"(d[1]), "+f"(d[2]), "+f"(d[3])
        : "r"(a[0]), "r"(a[1]), "r"(a[2]), "r"(a[3]), "r"(b[0]), "r"(b[1]));
}
__device__ __forceinline__ float rna_tf32(float x) {
    float r;
    asm("cvt.rna.tf32.f32 %0, %1;" : "=f"(r) : "f"(x));
    return r;
}
__device__ __forceinline__ float sigmoidf_(float x) { return 1.0f / (1.0f + __expf(-x)); }

// ---------------- stage fill ----------------
// A: BM x BK, SW128 swizzle: addr = row*128 + ((chunk ^ (row&7))*16), chunk=k/4
// B: BK x BN, row-major padded: addr = k*528 + n*4
template<int MODE>
__device__ __forceinline__ void fill_stage(int tid, uint32_t stA, uint32_t stB,
                                           int m0, int n0, int k0)
{
    // ---- A: row = tid>>1, 4 chunks ----
    const int row = tid >> 1;
    const int c0a = (tid & 1) * 4;
#pragma unroll
    for (int j = 0; j < 4; j++) {
        const int ch = c0a + j;
        const int kg = k0 + ch * 4;
        const float* src;
        if (MODE == 1)       src = g_rh + (size_t)(m0 + row) * U2 + kg;
        else if (kg < 2048)  src = g_xR + (size_t)(m0 + row) * U2 + kg;
        else                 src = g_hR + (size_t)(m0 + row) * U2 + (kg - 2048);
        cp16(stA + (uint32_t)(row << 7) + (uint32_t)(((ch ^ (row & 7)) << 4)), src);
    }
    // ---- B: k = tid>>3, 4 chunks of 4 n ----
    const int kb = tid >> 3;
    const int kg = k0 + kb;
    const float* brow;
    if (MODE == 1)       brow = g_WhR  + (size_t)kg * GL + 4096 + n0;
    else if (k0 < 2048)  brow = g_WinR + (size_t)kg * GL + n0;
    else                 brow = g_WhR  + (size_t)(kg - 2048) * GL + n0;
#pragma unroll
    for (int q = 0; q < 4; q++) {
        const int ch = (tid & 7) + 8 * q;      // 0..31, n = ch*4
        cp16(stB + (uint32_t)(kb * (BSTRIDE * 4)) + (uint32_t)(ch << 4), brow + ch * 4);
    }
}

// ---------------- GEMM + fused epilogues ----------------
// MODE 0: G = [x|h] @ [Win;Wh]; epilogue by n-region -> g_rh / g_U / g_XH
// MODE 1: ch = rh @ Wh[:,2u:]; epilogue h_t = u*h + (1-u)*tanh(ch+xh+bh) -> out
template<int MODE>
__global__ void __launch_bounds__(THREADS, 1)
gru_gemm(const float* __restrict__ h_exact, const float* __restrict__ bias,
         float* __restrict__ out)
{
    extern __shared__ char smem_raw[];
    const uint32_t base = (smem_u32(smem_raw) + 127u) & ~127u;

    const int tid  = threadIdx.x;
    const int lane = tid & 31;
    const int wid  = tid >> 5;
    const int warp_m = wid & 1;          // 0..1 -> 64-row halves
    const int warp_n = wid >> 1;         // 0..3 -> 32-col quarters

    const int n0 = blockIdx.x * BN;
    const int m0 = blockIdx.y * BM;
    const int K  = (MODE == 1) ? 2048 : (n0 < 4096 ? 4096 : 2048);
    const int NC = K / BK;

    // per-thread ldmatrix A addressing
    const int sel   = lane >> 3;                       // matrix select
    const int arow  = warp_m * 64 + (lane & 7) + ((sel & 1) << 3);
    const int cadd  = sel >> 1;                        // chunk low bit
    const int aswzr = lane & 7;                        // row&7 for swizzle

    // per-thread B lds addressing
    const int kq   = lane & 3;
    const int ncol = warp_n * 32 + (lane >> 2);

    float d[4][4][4];
#pragma unroll
    for (int mf = 0; mf < 4; mf++)
#pragma unroll
        for (int nf = 0; nf < 4; nf++)
#pragma unroll
            for (int r = 0; r < 4; r++) d[mf][nf][r] = 0.0f;

    // prologue
    fill_stage<MODE>(tid, base, base + A_STAGE_BYTES, m0, n0, 0);
    cp_commit();
    fill_stage<MODE>(tid, base + STAGE_BYTES, base + STAGE_BYTES + A_STAGE_BYTES, m0, n0, BK);
    cp_commit();

    int fs = 2;                                       // next fill stage index
    for (int c = 0; c < NC; c++) {
        if (c + 2 < NC) {
            const uint32_t sb = base + (uint32_t)fs * STAGE_BYTES;
            fill_stage<MODE>(tid, sb, sb + A_STAGE_BYTES, m0, n0, (c + 2) * BK);
        }
        cp_commit();
        cp_wait<2>();
        __syncthreads();

        const uint32_t cs  = base + (uint32_t)(c % 3) * STAGE_BYTES;
        const uint32_t stB = cs + A_STAGE_BYTES;

#pragma unroll
        for (int s = 0; s < 4; s++) {
            uint32_t a[4][4];
#pragma unroll
            for (int mf = 0; mf < 4; mf++) {
                const uint32_t addr = cs + (uint32_t)((arow + mf * 16) << 7)
                                    + (uint32_t)((((s << 1) + cadd) ^ aswzr) << 4);
                ldsm_x4(a[mf], addr);
            }
            uint32_t b[4][2];
#pragma unroll
            for (int nf = 0; nf < 4; nf++) {
                const uint32_t ba = stB + (uint32_t)((s * 8 + kq) * (BSTRIDE * 4))
                                  + (uint32_t)((ncol + nf * 8) << 2);
                b[nf][0] = lds32(ba);
                b[nf][1] = lds32(ba + 4u * (BSTRIDE * 4));
            }
#pragma unroll
            for (int mf = 0; mf < 4; mf++)
#pragma unroll
                for (int nf = 0; nf < 4; nf++)
                    mma_tf32(d[mf][nf], a[mf], b[nf]);
        }
        __syncthreads();
        fs = (fs + 1) % 3;
    }

    // ---------------- epilogue ----------------
    const int region = (MODE == 0) ? (n0 >> 11) : 2;

#pragma unroll
    for (int mf = 0; mf < 4; mf++) {
#pragma unroll
        for (int nf = 0; nf < 4; nf++) {
            const int gc = n0 + warp_n * 32 + nf * 8 + (lane & 3) * 2;  // global gate col
#pragma unroll
            for (int half = 0; half < 2; half++) {
                const int grow = m0 + warp_m * 64 + mf * 16 + (lane >> 2) + half * 8;
                const float v0 = d[mf][nf][half * 2 + 0];
                const float v1 = d[mf][nf][half * 2 + 1];
                const size_t rb = (size_t)grow * U2;

                if (MODE == 0) {
                    const int nl = gc & 2047;
                    if (region == 0) {
                        float2 bv = *(const float2*)(bias + gc);
                        float2 hv = *(const float2*)(h_exact + rb + nl);
                        float2 o;
                        o.x = rna_tf32(sigmoidf_(v0 + bv.x) * hv.x);
                        o.y = rna_tf32(sigmoidf_(v1 + bv.y) * hv.y);
                        *(float2*)(g_rh + rb + nl) = o;
                    } else if (region == 1) {
                        float2 bv = *(const float2*)(bias + gc);
                        float2 o;
                        o.x = sigmoidf_(v0 + bv.x);
                        o.y = sigmoidf_(v1 + bv.y);
                        *(float2*)(g_U + rb + nl) = o;
                    } else {
                        float2 o; o.x = v0; o.y = v1;
                        *(float2*)(g_XH + rb + nl) = o;
                    }
                } else {
                    float2 xh = *(const float2*)(g_XH + rb + gc);
                    float2 uu = *(const float2*)(g_U  + rb + gc);
                    float2 hv = *(const float2*)(h_exact + rb + gc);
                    float2 bv = *(const float2*)(bias + 4096 + gc);
                    float2 o;
                    const float c0 = tanhf(v0 + xh.x + bv.x);
                    const float c1 = tanhf(v1 + xh.y + bv.y);
                    o.x = uu.x * hv.x + (1.0f - uu.x) * c0;
                    o.y = uu.y * hv.y + (1.0f - uu.y) * c1;
                    *(float2*)(out + rb + gc) = o;
                }
            }
        }
    }
}

// ---------------- tf32 rounding pass ----------------
__global__ void __launch_bounds__(256)
round_tf32_kernel(const float4* __restrict__ in, float4* __restrict__ o, int n4)
{
    for (int i = blockIdx.x * blockDim.x + threadIdx.x; i < n4; i += gridDim.x * blockDim.x) {
        float4 v = in[i];
        v.x = rna_tf32(v.x); v.y = rna_tf32(v.y);
        v.z = rna_tf32(v.z); v.w = rna_tf32(v.w);
        o[i] = v;
    }
}

// ---------------- host ----------------
extern "C" void kernel_launch(void* const* d_in, const int* in_sizes, int n_in,
                              void* d_out, int out_size)
{
    const float* x    = (const float*)d_in[0];
    const float* h    = (const float*)d_in[1];
    const float* Win  = (const float*)d_in[2];
    const float* Wh   = (const float*)d_in[3];
    const float* bias = (const float*)d_in[4];
    float* out = (float*)d_out;

    float *xR, *hR, *WinR, *WhR;
    cudaGetSymbolAddress((void**)&xR,   g_xR);
    cudaGetSymbolAddress((void**)&hR,   g_hR);
    cudaGetSymbolAddress((void**)&WinR, g_WinR);
    cudaGetSymbolAddress((void**)&WhR,  g_WhR);

    cudaFuncSetAttribute(gru_gemm<0>, cudaFuncAttributeMaxDynamicSharedMemorySize, SMEM_ALLOC);
    cudaFuncSetAttribute(gru_gemm<1>, cudaFuncAttributeMaxDynamicSharedMemorySize, SMEM_ALLOC);

    const int nx4 = BATCH * U2 / 4;
    const int nw4 = U2 * GL / 4;
    round_tf32_kernel<<<4096, 256>>>((const float4*)x,   (float4*)xR,   nx4);
    round_tf32_kernel<<<4096, 256>>>((const float4*)h,   (float4*)hR,   nx4);
    round_tf32_kernel<<<4096, 256>>>((const float4*)Win, (float4*)WinR, nw4);
    round_tf32_kernel<<<4096, 256>>>((const float4*)Wh,  (float4*)WhR,  nw4);

    dim3 gA(GL / BN, BATCH / BM);   // 48 x 64
    gru_gemm<0><<<gA, THREADS, SMEM_ALLOC>>>(h, bias, out);

    dim3 gB(U2 / BN, BATCH / BM);   // 16 x 64
    gru_gemm<1><<<gB, THREADS, SMEM_ALLOC>>>(h, bias, out);
}

// round 4
// speedup vs baseline: 3.8050x; 1.3439x over previous
#include <cuda_runtime.h>
#include <math.h>
#include <stdint.h>

#define BATCH 8192
#define U2    2048
#define GL    6144

#define BM 128
#define BN 256
#define BK 32
#define STAGES 4
#define THREADS 256

#define A_STAGE_BYTES (BM * BK * 4)            // 16384, SW128-swizzled 128B rows
#define BSTRIDE 264                             // floats per B smem row (256+8 pad)
#define B_STAGE_BYTES (BK * BSTRIDE * 4)        // 33792
#define STAGE_BYTES (A_STAGE_BYTES + B_STAGE_BYTES)   // 50176
#define SMEM_ALLOC (STAGES * STAGE_BYTES + 256)       // ~200.9 KB

// tf32-rounded operand copies + intermediates (allocation-free scratch)
__device__ float g_xR [(size_t)BATCH * U2];
__device__ float g_hR [(size_t)BATCH * U2];
__device__ float g_WinR[(size_t)U2 * GL];
__device__ float g_WhR [(size_t)U2 * GL];
__device__ float g_rh [(size_t)BATCH * U2];   // tf32-rounded r*h
__device__ float g_U  [(size_t)BATCH * U2];   // update gate
__device__ float g_XH [(size_t)BATCH * U2];   // x@Win[:,2u:] raw

// ---------------- helpers ----------------
__device__ __forceinline__ uint32_t smem_u32(const void* p) {
    uint32_t a;
    asm("{ .reg .u64 t; cvta.to.shared.u64 t, %1; cvt.u32.u64 %0, t; }" : "=r"(a) : "l"(p));
    return a;
}
__device__ __forceinline__ void cp16(uint32_t dst, const void* src) {
    asm volatile("cp.async.cg.shared.global [%0], [%1], 16;" :: "r"(dst), "l"(src));
}
__device__ __forceinline__ void cp_commit() {
    asm volatile("cp.async.commit_group;" ::: "memory");
}
template<int N> __device__ __forceinline__ void cp_wait() {
    asm volatile("cp.async.wait_group %0;" :: "n"(N) : "memory");
}
__device__ __forceinline__ void ldsm_x4(uint32_t* r, uint32_t addr) {
    asm volatile("ldmatrix.sync.aligned.m8n8.x4.shared.b16 {%0,%1,%2,%3}, [%4];"
                 : "=r"(r[0]), "=r"(r[1]), "=r"(r[2]), "=r"(r[3]) : "r"(addr));
}
__device__ __forceinline__ uint32_t lds32(uint32_t addr) {
    uint32_t v;
    asm volatile("ld.shared.b32 %0, [%1];" : "=r"(v) : "r"(addr));
    return v;
}
__device__ __forceinline__ void mma_tf32(float* d, const uint32_t* a, const uint32_t* b) {
    asm volatile(
        "mma.sync.aligned.m16n8k8.row.col.f32.tf32.tf32.f32 "
        "{%0,%1,%2,%3}, {%4,%5,%6,%7}, {%8,%9}, {%0,%1,%2,%3};"
        : "+f"(d[0]), "+f"(d[1]), "+f"(d[2]), "+f"(d[3])
        : "r"(a[0]), "r"(a[1]), "r"(a[2]), "r"(a[3]), "r"(b[0]), "r"(b[1]));
}
__device__ __forceinline__ float rna_tf32(float x) {
    float r;
    asm("cvt.rna.tf32.f32 %0, %1;" : "=f"(r) : "f"(x));
    return r;
}
__device__ __forceinline__ float sigmoidf_(float x) { return 1.0f / (1.0f + __expf(-x)); }

// ---------------- stage fill ----------------
// A: BM x BK, SW128 swizzle: addr = row*128 + (((k/4) ^ (row&7))*16)
// B: BK x BN row-major, BSTRIDE=264 floats per row (conflict-free consume)
template<int MODE>
__device__ __forceinline__ void fill_stage(int tid, uint32_t stA, uint32_t stB,
                                           int m0, int n0, int k0)
{
    // ---- A: row = tid>>1, 4 chunks of k ----
    const int row = tid >> 1;
    const int c0a = (tid & 1) * 4;
#pragma unroll
    for (int j = 0; j < 4; j++) {
        const int ch = c0a + j;
        const int kg = k0 + ch * 4;
        const float* src;
        if (MODE == 1)       src = g_rh + (size_t)(m0 + row) * U2 + kg;
        else if (kg < 2048)  src = g_xR + (size_t)(m0 + row) * U2 + kg;
        else                 src = g_hR + (size_t)(m0 + row) * U2 + (kg - 2048);
        cp16(stA + (uint32_t)(row << 7) + (uint32_t)(((ch ^ (row & 7)) << 4)), src);
    }
    // ---- B: k-row = tid>>3, 8 float4 chunks across 256 n ----
    const int kb = tid >> 3;
    const int kg = k0 + kb;
    const float* brow;
    if (MODE == 1)       brow = g_WhR  + (size_t)kg * GL + 4096 + n0;
    else if (k0 < 2048)  brow = g_WinR + (size_t)kg * GL + n0;
    else                 brow = g_WhR  + (size_t)(kg - 2048) * GL + n0;
    const uint32_t bbase = stB + (uint32_t)(kb * (BSTRIDE * 4)) + (uint32_t)((tid & 7) << 4);
#pragma unroll
    for (int q = 0; q < 8; q++)
        cp16(bbase + (uint32_t)(q << 7), brow + (tid & 7) * 4 + q * 32);
}

// ---------------- GEMM + fused epilogues ----------------
// MODE 0: G = [x|h] @ [Win;Wh]; epilogue by n-region -> g_rh / g_U / g_XH
// MODE 1: ch = rh @ Wh[:,2u:]; epilogue h_t = u*h + (1-u)*tanh(ch+xh+bh) -> out
template<int MODE>
__global__ void __launch_bounds__(THREADS, 1)
gru_gemm(const float* __restrict__ h_exact, const float* __restrict__ bias,
         float* __restrict__ out)
{
    extern __shared__ char smem_raw[];
    const uint32_t base = (smem_u32(smem_raw) + 127u) & ~127u;

    const int tid  = threadIdx.x;
    const int lane = tid & 31;
    const int wid  = tid >> 5;
    const int warp_m = wid & 1;          // 0..1 -> 64-row halves
    const int warp_n = wid >> 1;         // 0..3 -> 64-col quarters

    const int n0 = blockIdx.x * BN;
    const int m0 = blockIdx.y * BM;
    const int K  = (MODE == 1) ? 2048 : (n0 < 4096 ? 4096 : 2048);
    const int NC = K / BK;

    // per-thread ldmatrix A addressing
    const int sel   = lane >> 3;
    const int arow  = warp_m * 64 + (lane & 7) + ((sel & 1) << 3);
    const int cadd  = sel >> 1;
    const int aswzr = lane & 7;

    // per-thread B lds addressing
    const int kq   = lane & 3;
    const int ncol = warp_n * 64 + (lane >> 2);

    float d[4][8][4];
#pragma unroll
    for (int mf = 0; mf < 4; mf++)
#pragma unroll
        for (int nf = 0; nf < 8; nf++)
#pragma unroll
            for (int r = 0; r < 4; r++) d[mf][nf][r] = 0.0f;

    // prologue: fill stages 0,1
    fill_stage<MODE>(tid, base, base + A_STAGE_BYTES, m0, n0, 0);
    cp_commit();
    fill_stage<MODE>(tid, base + STAGE_BYTES, base + STAGE_BYTES + A_STAGE_BYTES, m0, n0, BK);
    cp_commit();

    for (int c = 0; c < NC; c++) {
        if (c + 2 < NC) {
            const uint32_t sb = base + (uint32_t)((c + 2) % STAGES) * STAGE_BYTES;
            fill_stage<MODE>(tid, sb, sb + A_STAGE_BYTES, m0, n0, (c + 2) * BK);
        }
        cp_commit();
        cp_wait<2>();
        __syncthreads();

        const uint32_t cs  = base + (uint32_t)(c % STAGES) * STAGE_BYTES;
        const uint32_t stB = cs + A_STAGE_BYTES;

#pragma unroll
        for (int s = 0; s < 4; s++) {
            uint32_t a[4][4];
#pragma unroll
            for (int mf = 0; mf < 4; mf++) {
                const uint32_t addr = cs + (uint32_t)((arow + mf * 16) << 7)
                                    + (uint32_t)((((s << 1) + cadd) ^ aswzr) << 4);
                ldsm_x4(a[mf], addr);
            }
            uint32_t b[8][2];
#pragma unroll
            for (int nf = 0; nf < 8; nf++) {
                const uint32_t ba = stB + (uint32_t)((s * 8 + kq) * (BSTRIDE * 4))
                                  + (uint32_t)((ncol + nf * 8) << 2);
                b[nf][0] = lds32(ba);
                b[nf][1] = lds32(ba + 4u * (BSTRIDE * 4));
            }
#pragma unroll
            for (int mf = 0; mf < 4; mf++)
#pragma unroll
                for (int nf = 0; nf < 8; nf++)
                    mma_tf32(d[mf][nf], a[mf], b[nf]);
        }
    }

    // ---------------- epilogue ----------------
    const int region = (MODE == 0) ? (n0 >> 11) : 2;

#pragma unroll
    for (int mf = 0; mf < 4; mf++) {
#pragma unroll
        for (int nf = 0; nf < 8; nf++) {
            const int gc = n0 + warp_n * 64 + nf * 8 + (lane & 3) * 2;
#pragma unroll
            for (int half = 0; half < 2; half++) {
                const int grow = m0 + warp_m * 64 + mf * 16 + (lane >> 2) + half * 8;
                const float v0 = d[mf][nf][half * 2 + 0];
                const float v1 = d[mf][nf][half * 2 + 1];
                const size_t rb = (size_t)grow * U2;

                if (MODE == 0) {
                    const int nl = gc & 2047;
                    if (region == 0) {
                        float2 bv = *(const float2*)(bias + gc);
                        float2 hv = *(const float2*)(h_exact + rb + nl);
                        float2 o;
                        o.x = rna_tf32(sigmoidf_(v0 + bv.x) * hv.x);
                        o.y = rna_tf32(sigmoidf_(v1 + bv.y) * hv.y);
                        *(float2*)(g_rh + rb + nl) = o;
                    } else if (region == 1) {
                        float2 bv = *(const float2*)(bias + gc);
                        float2 o;
                        o.x = sigmoidf_(v0 + bv.x);
                        o.y = sigmoidf_(v1 + bv.y);
                        *(float2*)(g_U + rb + nl) = o;
                    } else {
                        float2 o; o.x = v0; o.y = v1;
                        *(float2*)(g_XH + rb + nl) = o;
                    }
                } else {
                    float2 xh = *(const float2*)(g_XH + rb + gc);
                    float2 uu = *(const float2*)(g_U  + rb + gc);
                    float2 hv = *(const float2*)(h_exact + rb + gc);
                    float2 bv = *(const float2*)(bias + 4096 + gc);
                    float2 o;
                    const float c0 = tanhf(v0 + xh.x + bv.x);
                    const float c1 = tanhf(v1 + xh.y + bv.y);
                    o.x = uu.x * hv.x + (1.0f - uu.x) * c0;
                    o.y = uu.y * hv.y + (1.0f - uu.y) * c1;
                    *(float2*)(out + rb + gc) = o;
                }
            }
        }
    }
}

// ---------------- tf32 rounding pass ----------------
__global__ void __launch_bounds__(256)
round_tf32_kernel(const float4* __restrict__ in, float4* __restrict__ o, int n4)
{
    for (int i = blockIdx.x * blockDim.x + threadIdx.x; i < n4; i += gridDim.x * blockDim.x) {
        float4 v = in[i];
        v.x = rna_tf32(v.x); v.y = rna_tf32(v.y);
        v.z = rna_tf32(v.z); v.w = rna_tf32(v.w);
        o[i] = v;
    }
}

// ---------------- host ----------------
extern "C" void kernel_launch(void* const* d_in, const int* in_sizes, int n_in,
                              void* d_out, int out_size)
{
    const float* x    = (const float*)d_in[0];
    const float* h    = (const float*)d_in[1];
    const float* Win  = (const float*)d_in[2];
    const float* Wh   = (const float*)d_in[3];
    const float* bias = (const float*)d_in[4];
    float* out = (float*)d_out;

    float *xR, *hR, *WinR, *WhR;
    cudaGetSymbolAddress((void**)&xR,   g_xR);
    cudaGetSymbolAddress((void**)&hR,   g_hR);
    cudaGetSymbolAddress((void**)&WinR, g_WinR);
    cudaGetSymbolAddress((void**)&WhR,  g_WhR);

    cudaFuncSetAttribute(gru_gemm<0>, cudaFuncAttributeMaxDynamicSharedMemorySize, SMEM_ALLOC);
    cudaFuncSetAttribute(gru_gemm<1>, cudaFuncAttributeMaxDynamicSharedMemorySize, SMEM_ALLOC);

    const int nx4 = BATCH * U2 / 4;
    const int nw4 = U2 * GL / 4;
    round_tf32_kernel<<<4096, 256>>>((const float4*)x,   (float4*)xR,   nx4);
    round_tf32_kernel<<<4096, 256>>>((const float4*)h,   (float4*)hR,   nx4);
    round_tf32_kernel<<<4096, 256>>>((const float4*)Win, (float4*)WinR, nw4);
    round_tf32_kernel<<<4096, 256>>>((const float4*)Wh,  (float4*)WhR,  nw4);

    dim3 gA(GL / BN, BATCH / BM);   // 24 x 64
    gru_gemm<0><<<gA, THREADS, SMEM_ALLOC>>>(h, bias, out);

    dim3 gB(U2 / BN, BATCH / BM);   // 8 x 64
    gru_gemm<1><<<gB, THREADS, SMEM_ALLOC>>>(h, bias, out);
}

// round 5
// speedup vs baseline: 6.2611x; 1.6455x over previous
#include <cuda_runtime.h>
#include <cuda_fp16.h>
#include <math.h>
#include <stdint.h>

#define BATCH 8192
#define U2    2048
#define GL    6144

#define BM 128
#define BN 256
#define BK 64
#define STAGES 4
#define THREADS 256

#define A_STAGE_BYTES (BM * BK * 2)            // 16384: 128 rows x 128B, SW128
#define BROWB 528                               // B smem row bytes (512 data + 16 pad)
#define B_STAGE_BYTES (BK * BROWB)              // 33792
#define STAGE_BYTES (A_STAGE_BYTES + B_STAGE_BYTES)   // 50176
#define SMEM_ALLOC (STAGES * STAGE_BYTES + 256)

// fp16 operand copies + intermediates (allocation-free scratch)
__device__ __half g_xH [(size_t)BATCH * U2];
__device__ __half g_hH [(size_t)BATCH * U2];
__device__ __half g_WinH[(size_t)U2 * GL];
__device__ __half g_WhH [(size_t)U2 * GL];
__device__ __half g_rhH[(size_t)BATCH * U2];   // fp16 r*h
__device__ float  g_U  [(size_t)BATCH * U2];   // update gate (fp32)
__device__ float  g_XH [(size_t)BATCH * U2];   // x@Win[:,2u:] (fp32)

// ---------------- helpers ----------------
__device__ __forceinline__ uint32_t smem_u32(const void* p) {
    uint32_t a;
    asm("{ .reg .u64 t; cvta.to.shared.u64 t, %1; cvt.u32.u64 %0, t; }" : "=r"(a) : "l"(p));
    return a;
}
__device__ __forceinline__ void cp16(uint32_t dst, const void* src) {
    asm volatile("cp.async.cg.shared.global [%0], [%1], 16;" :: "r"(dst), "l"(src));
}
__device__ __forceinline__ void cp_commit() {
    asm volatile("cp.async.commit_group;" ::: "memory");
}
template<int N> __device__ __forceinline__ void cp_wait() {
    asm volatile("cp.async.wait_group %0;" :: "n"(N) : "memory");
}
__device__ __forceinline__ void ldsm_x4(uint32_t* r, uint32_t addr) {
    asm volatile("ldmatrix.sync.aligned.m8n8.x4.shared.b16 {%0,%1,%2,%3}, [%4];"
                 : "=r"(r[0]), "=r"(r[1]), "=r"(r[2]), "=r"(r[3]) : "r"(addr));
}
__device__ __forceinline__ void ldsm_x4_t(uint32_t* r, uint32_t addr) {
    asm volatile("ldmatrix.sync.aligned.m8n8.x4.trans.shared.b16 {%0,%1,%2,%3}, [%4];"
                 : "=r"(r[0]), "=r"(r[1]), "=r"(r[2]), "=r"(r[3]) : "r"(addr));
}
__device__ __forceinline__ void mma_f16(float* d, const uint32_t* a, const uint32_t* b) {
    asm volatile(
        "mma.sync.aligned.m16n8k16.row.col.f32.f16.f16.f32 "
        "{%0,%1,%2,%3}, {%4,%5,%6,%7}, {%8,%9}, {%0,%1,%2,%3};"
        : "+f"(d[0]), "+f"(d[1]), "+f"(d[2]), "+f"(d[3])
        : "r"(a[0]), "r"(a[1]), "r"(a[2]), "r"(a[3]), "r"(b[0]), "r"(b[1]));
}
__device__ __forceinline__ float sigmoidf_(float x) { return 1.0f / (1.0f + __expf(-x)); }

// ---------------- stage fill ----------------
// A: BM x BK fp16, 128B rows, SW128: dst = row*128 + (((k/8) ^ (row&7))*16)
// B: BK x BN fp16, k-major rows of 512B data padded to 528B
template<int MODE>
__device__ __forceinline__ void fill_stage(int tid, uint32_t stA, uint32_t stB,
                                           int m0, int n0, int k0)
{
    // ---- A: row = tid>>1, 4 x 16B chunks (8 fp16 each) ----
    const int row = tid >> 1;
    const int c0a = (tid & 1) * 4;
#pragma unroll
    for (int j = 0; j < 4; j++) {
        const int ch = c0a + j;                  // 0..7
        const int kg = k0 + ch * 8;
        const __half* src;
        if (MODE == 1)       src = g_rhH + (size_t)(m0 + row) * U2 + kg;
        else if (kg < 2048)  src = g_xH  + (size_t)(m0 + row) * U2 + kg;
        else                 src = g_hH  + (size_t)(m0 + row) * U2 + (kg - 2048);
        cp16(stA + (uint32_t)(row << 7) + (uint32_t)(((ch ^ (row & 7)) << 4)), src);
    }
    // ---- B: k-row = tid>>2 (0..63), 8 x 16B chunks across 256 n ----
    const int kb = tid >> 2;
    const int kg = k0 + kb;
    const __half* brow;
    if (MODE == 1)       brow = g_WhH  + (size_t)kg * GL + 4096 + n0;
    else if (k0 < 2048)  brow = g_WinH + (size_t)kg * GL + n0;
    else                 brow = g_WhH  + (size_t)(kg - 2048) * GL + n0;
    const uint32_t bbase = stB + (uint32_t)(kb * BROWB) + (uint32_t)((tid & 3) << 4);
#pragma unroll
    for (int q = 0; q < 8; q++)
        cp16(bbase + (uint32_t)(q << 6), brow + (tid & 3) * 8 + q * 32);
}

// ---------------- GEMM + fused epilogues ----------------
// MODE 0: G = [x|h] @ [Win;Wh]; epilogue by n-region -> g_rhH / g_U / g_XH
// MODE 1: ch = rh @ Wh[:,2u:]; epilogue h_t = u*h + (1-u)*tanh(ch+xh+bh) -> out
template<int MODE>
__global__ void __launch_bounds__(THREADS, 1)
gru_gemm(const float* __restrict__ h_exact, const float* __restrict__ bias,
         float* __restrict__ out)
{
    extern __shared__ char smem_raw[];
    const uint32_t base = (smem_u32(smem_raw) + 127u) & ~127u;

    const int tid  = threadIdx.x;
    const int lane = tid & 31;
    const int wid  = tid >> 5;
    const int warp_m = wid & 1;          // 64-row halves
    const int warp_n = wid >> 1;         // 64-col quarters

    const int n0 = blockIdx.x * BN;
    const int m0 = blockIdx.y * BM;
    const int K  = (MODE == 1) ? 2048 : (n0 < 4096 ? 4096 : 2048);
    const int NC = K / BK;

    // ldmatrix lane decomposition
    const int g = lane >> 3;             // matrix group 0..3
    const int r = lane & 7;              // row within group
    // A (non-trans): m_local = (g&1)*8 + r, k-half = g>>1
    const int a_mlocal = ((g & 1) << 3) + r;
    const int a_khalf  = g >> 1;
    const uint32_t a_rowoff = (uint32_t)((warp_m * 64 + a_mlocal) << 7);
    // B (trans): k_local = (g&1)*8 + r, n_oct = g>>1
    const int b_klocal = ((g & 1) << 3) + r;
    const int b_noct   = g >> 1;

    float d[4][8][4];
#pragma unroll
    for (int mf = 0; mf < 4; mf++)
#pragma unroll
        for (int nf = 0; nf < 8; nf++)
#pragma unroll
            for (int q = 0; q < 4; q++) d[mf][nf][q] = 0.0f;

    // prologue: fill stages 0,1
    fill_stage<MODE>(tid, base, base + A_STAGE_BYTES, m0, n0, 0);
    cp_commit();
    fill_stage<MODE>(tid, base + STAGE_BYTES, base + STAGE_BYTES + A_STAGE_BYTES, m0, n0, BK);
    cp_commit();

    for (int c = 0; c < NC; c++) {
        if (c + 2 < NC) {
            const uint32_t sb = base + (uint32_t)((c + 2) % STAGES) * STAGE_BYTES;
            fill_stage<MODE>(tid, sb, sb + A_STAGE_BYTES, m0, n0, (c + 2) * BK);
        }
        cp_commit();
        cp_wait<2>();
        __syncthreads();

        const uint32_t cs  = base + (uint32_t)(c % STAGES) * STAGE_BYTES;
        const uint32_t stB = cs + A_STAGE_BYTES;

#pragma unroll
        for (int ks = 0; ks < 4; ks++) {           // k16 steps
            uint32_t a[4][4];
#pragma unroll
            for (int mf = 0; mf < 4; mf++) {
                const uint32_t addr = cs + a_rowoff + (uint32_t)(mf << 11)
                                    + (uint32_t)((((ks << 1) + a_khalf) ^ r) << 4);
                ldsm_x4(a[mf], addr);
            }
            uint32_t b[8][2];
#pragma unroll
            for (int pr = 0; pr < 4; pr++) {       // 16-n groups
                uint32_t bb[4];
                const uint32_t addr = stB
                    + (uint32_t)((ks * 16 + b_klocal) * BROWB)
                    + (uint32_t)((warp_n * 64 + pr * 16 + b_noct * 8) << 1);
                ldsm_x4_t(bb, addr);
                b[pr * 2 + 0][0] = bb[0]; b[pr * 2 + 0][1] = bb[1];
                b[pr * 2 + 1][0] = bb[2]; b[pr * 2 + 1][1] = bb[3];
            }
#pragma unroll
            for (int mf = 0; mf < 4; mf++)
#pragma unroll
                for (int nf = 0; nf < 8; nf++)
                    mma_f16(d[mf][nf], a[mf], b[nf]);
        }
    }

    // ---------------- epilogue ----------------
    const int region = (MODE == 0) ? (n0 >> 11) : 2;

#pragma unroll
    for (int mf = 0; mf < 4; mf++) {
#pragma unroll
        for (int nf = 0; nf < 8; nf++) {
            const int gc = n0 + warp_n * 64 + nf * 8 + (lane & 3) * 2;
#pragma unroll
            for (int half = 0; half < 2; half++) {
                const int grow = m0 + warp_m * 64 + mf * 16 + (lane >> 2) + half * 8;
                const float v0 = d[mf][nf][half * 2 + 0];
                const float v1 = d[mf][nf][half * 2 + 1];
                const size_t rb = (size_t)grow * U2;

                if (MODE == 0) {
                    const int nl = gc & 2047;
                    if (region == 0) {
                        float2 bv = *(const float2*)(bias + gc);
                        float2 hv = *(const float2*)(h_exact + rb + nl);
                        __half2 o = __floats2half2_rn(sigmoidf_(v0 + bv.x) * hv.x,
                                                      sigmoidf_(v1 + bv.y) * hv.y);
                        *(__half2*)(g_rhH + rb + nl) = o;
                    } else if (region == 1) {
                        float2 bv = *(const float2*)(bias + gc);
                        float2 o;
                        o.x = sigmoidf_(v0 + bv.x);
                        o.y = sigmoidf_(v1 + bv.y);
                        *(float2*)(g_U + rb + nl) = o;
                    } else {
                        float2 o; o.x = v0; o.y = v1;
                        *(float2*)(g_XH + rb + nl) = o;
                    }
                } else {
                    float2 xh = *(const float2*)(g_XH + rb + gc);
                    float2 uu = *(const float2*)(g_U  + rb + gc);
                    float2 hv = *(const float2*)(h_exact + rb + gc);
                    float2 bv = *(const float2*)(bias + 4096 + gc);
                    float2 o;
                    const float c0 = tanhf(v0 + xh.x + bv.x);
                    const float c1 = tanhf(v1 + xh.y + bv.y);
                    o.x = uu.x * hv.x + (1.0f - uu.x) * c0;
                    o.y = uu.y * hv.y + (1.0f - uu.y) * c1;
                    *(float2*)(out + rb + gc) = o;
                }
            }
        }
    }
}

// ---------------- fp32 -> fp16 conversion pass ----------------
__global__ void __launch_bounds__(256)
cvt_half_kernel(const float4* __restrict__ in, __half2* __restrict__ o, int n4)
{
    for (int i = blockIdx.x * blockDim.x + threadIdx.x; i < n4; i += gridDim.x * blockDim.x) {
        float4 v = in[i];
        o[2 * i + 0] = __floats2half2_rn(v.x, v.y);
        o[2 * i + 1] = __floats2half2_rn(v.z, v.w);
    }
}

// ---------------- host ----------------
extern "C" void kernel_launch(void* const* d_in, const int* in_sizes, int n_in,
                              void* d_out, int out_size)
{
    const float* x    = (const float*)d_in[0];
    const float* h    = (const float*)d_in[1];
    const float* Win  = (const float*)d_in[2];
    const float* Wh   = (const float*)d_in[3];
    const float* bias = (const float*)d_in[4];
    float* out = (float*)d_out;

    __half *xH, *hH, *WinH, *WhH;
    cudaGetSymbolAddress((void**)&xH,   g_xH);
    cudaGetSymbolAddress((void**)&hH,   g_hH);
    cudaGetSymbolAddress((void**)&WinH, g_WinH);
    cudaGetSymbolAddress((void**)&WhH,  g_WhH);

    cudaFuncSetAttribute(gru_gemm<0>, cudaFuncAttributeMaxDynamicSharedMemorySize, SMEM_ALLOC);
    cudaFuncSetAttribute(gru_gemm<1>, cudaFuncAttributeMaxDynamicSharedMemorySize, SMEM_ALLOC);

    const int nx4 = BATCH * U2 / 4;
    const int nw4 = U2 * GL / 4;
    cvt_half_kernel<<<4096, 256>>>((const float4*)x,   (__half2*)xH,   nx4);
    cvt_half_kernel<<<4096, 256>>>((const float4*)h,   (__half2*)hH,   nx4);
    cvt_half_kernel<<<4096, 256>>>((const float4*)Win, (__half2*)WinH, nw4);
    cvt_half_kernel<<<4096, 256>>>((const float4*)Wh,  (__half2*)WhH,  nw4);

    dim3 gA(GL / BN, BATCH / BM);   // 24 x 64
    gru_gemm<0><<<gA, THREADS, SMEM_ALLOC>>>(h, bias, out);

    dim3 gB(U2 / BN, BATCH / BM);   // 8 x 64
    gru_gemm<1><<<gB, THREADS, SMEM_ALLOC>>>(h, bias, out);
}

// round 6
// speedup vs baseline: 6.7840x; 1.0835x over previous
#include <cuda_runtime.h>
#include <cuda_fp16.h>
#include <math.h>
#include <stdint.h>

#define BATCH 8192
#define U2    2048
#define GL    6144

#define BM 128
#define BN 256
#define BK 64
#define STAGES 4
#define THREADS 256

#define A_STAGE_BYTES (BM * BK * 2)            // 16384: 128 rows x 128B, SW128
#define BROWB 528                               // B smem row bytes (512 data + 16 pad)
#define B_STAGE_BYTES (BK * BROWB)              // 33792
#define STAGE_BYTES (A_STAGE_BYTES + B_STAGE_BYTES)   // 50176
#define SMEM_ALLOC (STAGES * STAGE_BYTES + 256)

#define NT_A 1536      // A tiles: 64 m-blocks x 24 n-tiles (m-major)
#define NTOT 2048      // + 512 B tiles: 64 m-blocks x 8 n-tiles

// fp16 operand copies + intermediates (allocation-free scratch)
__device__ __half g_xH [(size_t)BATCH * U2];
__device__ __half g_hH [(size_t)BATCH * U2];
__device__ __half g_WinH[(size_t)U2 * GL];
__device__ __half g_WhH [(size_t)U2 * GL];
__device__ __half g_rhH[(size_t)BATCH * U2];   // fp16 r*h
__device__ float  g_U  [(size_t)BATCH * U2];   // update gate (fp32)
__device__ float  g_XH [(size_t)BATCH * U2];   // x@Win[:,2u:] (fp32)

// scheduling state (zeroed per launch by init kernel)
__device__ unsigned g_work;
__device__ unsigned g_done[64];

// ---------------- helpers ----------------
__device__ __forceinline__ uint32_t smem_u32(const void* p) {
    uint32_t a;
    asm("{ .reg .u64 t; cvta.to.shared.u64 t, %1; cvt.u32.u64 %0, t; }" : "=r"(a) : "l"(p));
    return a;
}
__device__ __forceinline__ void cp16(uint32_t dst, const void* src) {
    asm volatile("cp.async.cg.shared.global [%0], [%1], 16;" :: "r"(dst), "l"(src));
}
__device__ __forceinline__ void cp_commit() {
    asm volatile("cp.async.commit_group;" ::: "memory");
}
template<int N> __device__ __forceinline__ void cp_wait() {
    asm volatile("cp.async.wait_group %0;" :: "n"(N) : "memory");
}
__device__ __forceinline__ void ldsm_x4(uint32_t* r, uint32_t addr) {
    asm volatile("ldmatrix.sync.aligned.m8n8.x4.shared.b16 {%0,%1,%2,%3}, [%4];"
                 : "=r"(r[0]), "=r"(r[1]), "=r"(r[2]), "=r"(r[3]) : "r"(addr));
}
__device__ __forceinline__ void ldsm_x4_t(uint32_t* r, uint32_t addr) {
    asm volatile("ldmatrix.sync.aligned.m8n8.x4.trans.shared.b16 {%0,%1,%2,%3}, [%4];"
                 : "=r"(r[0]), "=r"(r[1]), "=r"(r[2]), "=r"(r[3]) : "r"(addr));
}
__device__ __forceinline__ void mma_f16(float* d, const uint32_t* a, const uint32_t* b) {
    asm volatile(
        "mma.sync.aligned.m16n8k16.row.col.f32.f16.f16.f32 "
        "{%0,%1,%2,%3}, {%4,%5,%6,%7}, {%8,%9}, {%0,%1,%2,%3};"
        : "+f"(d[0]), "+f"(d[1]), "+f"(d[2]), "+f"(d[3])
        : "r"(a[0]), "r"(a[1]), "r"(a[2]), "r"(a[3]), "r"(b[0]), "r"(b[1]));
}
__device__ __forceinline__ float sigmoidf_(float x) { return 1.0f / (1.0f + __expf(-x)); }

// ---------------- stage fill ----------------
__device__ __forceinline__ void fill_stage(int tid, uint32_t stA, uint32_t stB,
                                           int m0, int k0,
                                           const __half* aptr0, const __half* aptr1,
                                           const __half* bp0, const __half* bp1)
{
    // ---- A: row = tid>>1, 4 x 16B chunks (8 fp16 each) ----
    const int row = tid >> 1;
    const int c0a = (tid & 1) * 4;
#pragma unroll
    for (int j = 0; j < 4; j++) {
        const int ch = c0a + j;                  // 0..7
        const int kg = k0 + ch * 8;
        const __half* src = (kg < 2048)
            ? aptr0 + (size_t)(m0 + row) * U2 + kg
            : aptr1 + (size_t)(m0 + row) * U2 + (kg - 2048);
        cp16(stA + (uint32_t)(row << 7) + (uint32_t)(((ch ^ (row & 7)) << 4)), src);
    }
    // ---- B: k-row = tid>>2 (0..63), 8 x 16B chunks across 256 n ----
    const int kb = tid >> 2;
    const int kg = k0 + kb;
    const __half* brow = (kg < 2048)
        ? bp0 + (size_t)kg * GL
        : bp1 + (size_t)(kg - 2048) * GL;
    const uint32_t bbase = stB + (uint32_t)(kb * BROWB) + (uint32_t)((tid & 3) << 4);
#pragma unroll
    for (int q = 0; q < 8; q++)
        cp16(bbase + (uint32_t)(q << 6), brow + (tid & 3) * 8 + q * 32);
}

// ---------------- fused persistent GRU kernel ----------------
__global__ void __launch_bounds__(THREADS, 1)
gru_fused(const float* __restrict__ h_exact, const float* __restrict__ bias,
          float* __restrict__ out)
{
    extern __shared__ char smem_raw[];
    const uint32_t base = (smem_u32(smem_raw) + 127u) & ~127u;
    volatile int* sm_bcast = (volatile int*)(smem_raw + STAGES * STAGE_BYTES + 128);

    const int tid  = threadIdx.x;
    const int lane = tid & 31;
    const int wid  = tid >> 5;
    const int warp_m = wid & 1;
    const int warp_n = wid >> 1;

    // ldmatrix lane decomposition
    const int g = lane >> 3;
    const int r = lane & 7;
    const int a_mlocal = ((g & 1) << 3) + r;
    const int a_khalf  = g >> 1;
    const uint32_t a_rowoff = (uint32_t)((warp_m * 64 + a_mlocal) << 7);
    const int b_klocal = ((g & 1) << 3) + r;
    const int b_noct   = g >> 1;

    for (;;) {
        // ---- grab a tile ----
        if (tid == 0) *sm_bcast = (int)atomicAdd(&g_work, 1u);
        __syncthreads();
        const int t = *sm_bcast;
        if (t >= NTOT) break;

        // ---- decode ----
        int mblk, n0, K, region;
        const __half *aptr0, *aptr1, *bp0, *bp1;
        if (t < NT_A) {
            mblk = t / 24;
            const int nt = t % 24;
            n0 = nt * 256;                       // global gate column base (0..6143)
            K  = (nt < 16) ? 4096 : 2048;
            region = n0 >> 11;                   // 0=r, 1=u, 2=xh
            aptr0 = g_xH;  aptr1 = g_hH;
            bp0 = g_WinH + n0;  bp1 = g_WhH + n0;
        } else {
            const int u = t - NT_A;
            mblk = u / 8;
            n0 = (u % 8) * 256;                  // output column base (0..2047)
            K = 2048; region = 3;
            aptr0 = g_rhH;  aptr1 = g_rhH;
            bp0 = g_WhH + 4096 + n0;  bp1 = bp0;
            // wait for all 24 A tiles of this m-block
            if (tid == 0) {
                while (atomicAdd(&g_done[mblk], 0u) < 24u) __nanosleep(128);
            }
            __syncthreads();
            __threadfence();
        }
        const int m0 = mblk * 128;
        const int NC = K / BK;

        float d[4][8][4];
#pragma unroll
        for (int mf = 0; mf < 4; mf++)
#pragma unroll
            for (int nf = 0; nf < 8; nf++)
#pragma unroll
                for (int q = 0; q < 4; q++) d[mf][nf][q] = 0.0f;

        // ---- pipeline prologue ----
        fill_stage(tid, base, base + A_STAGE_BYTES, m0, 0, aptr0, aptr1, bp0, bp1);
        cp_commit();
        fill_stage(tid, base + STAGE_BYTES, base + STAGE_BYTES + A_STAGE_BYTES,
                   m0, BK, aptr0, aptr1, bp0, bp1);
        cp_commit();

        // ---- main K loop ----
        for (int c = 0; c < NC; c++) {
            if (c + 2 < NC) {
                const uint32_t sb = base + (uint32_t)((c + 2) % STAGES) * STAGE_BYTES;
                fill_stage(tid, sb, sb + A_STAGE_BYTES, m0, (c + 2) * BK,
                           aptr0, aptr1, bp0, bp1);
            }
            cp_commit();
            cp_wait<2>();
            __syncthreads();

            const uint32_t cs  = base + (uint32_t)(c % STAGES) * STAGE_BYTES;
            const uint32_t stB = cs + A_STAGE_BYTES;

#pragma unroll
            for (int ks = 0; ks < 4; ks++) {
                uint32_t a[4][4];
#pragma unroll
                for (int mf = 0; mf < 4; mf++) {
                    const uint32_t addr = cs + a_rowoff + (uint32_t)(mf << 11)
                                        + (uint32_t)((((ks << 1) + a_khalf) ^ r) << 4);
                    ldsm_x4(a[mf], addr);
                }
                uint32_t b[8][2];
#pragma unroll
                for (int pr = 0; pr < 4; pr++) {
                    uint32_t bb[4];
                    const uint32_t addr = stB
                        + (uint32_t)((ks * 16 + b_klocal) * BROWB)
                        + (uint32_t)((warp_n * 64 + pr * 16 + b_noct * 8) << 1);
                    ldsm_x4_t(bb, addr);
                    b[pr * 2 + 0][0] = bb[0]; b[pr * 2 + 0][1] = bb[1];
                    b[pr * 2 + 1][0] = bb[2]; b[pr * 2 + 1][1] = bb[3];
                }
#pragma unroll
                for (int mf = 0; mf < 4; mf++)
#pragma unroll
                    for (int nf = 0; nf < 8; nf++)
                        mma_f16(d[mf][nf], a[mf], b[nf]);
            }
        }
        cp_wait<0>();

        // ---- epilogue ----
#pragma unroll
        for (int mf = 0; mf < 4; mf++) {
#pragma unroll
            for (int nf = 0; nf < 8; nf++) {
                const int gc = n0 + warp_n * 64 + nf * 8 + (lane & 3) * 2;
#pragma unroll
                for (int half = 0; half < 2; half++) {
                    const int grow = m0 + warp_m * 64 + mf * 16 + (lane >> 2) + half * 8;
                    const float v0 = d[mf][nf][half * 2 + 0];
                    const float v1 = d[mf][nf][half * 2 + 1];
                    const size_t rb = (size_t)grow * U2;

                    if (region == 0) {
                        const int nl = gc & 2047;
                        float2 bv = *(const float2*)(bias + gc);
                        float2 hv = *(const float2*)(h_exact + rb + nl);
                        __half2 o = __floats2half2_rn(sigmoidf_(v0 + bv.x) * hv.x,
                                                      sigmoidf_(v1 + bv.y) * hv.y);
                        *(__half2*)(g_rhH + rb + nl) = o;
                    } else if (region == 1) {
                        const int nl = gc & 2047;
                        float2 bv = *(const float2*)(bias + gc);
                        float2 o;
                        o.x = sigmoidf_(v0 + bv.x);
                        o.y = sigmoidf_(v1 + bv.y);
                        *(float2*)(g_U + rb + nl) = o;
                    } else if (region == 2) {
                        const int nl = gc & 2047;
                        float2 o; o.x = v0; o.y = v1;
                        *(float2*)(g_XH + rb + nl) = o;
                    } else {
                        float2 xh = *(const float2*)(g_XH + rb + gc);
                        float2 uu = *(const float2*)(g_U  + rb + gc);
                        float2 hv = *(const float2*)(h_exact + rb + gc);
                        float2 bv = *(const float2*)(bias + 4096 + gc);
                        float2 o;
                        const float c0 = tanhf(v0 + xh.x + bv.x);
                        const float c1 = tanhf(v1 + xh.y + bv.y);
                        o.x = uu.x * hv.x + (1.0f - uu.x) * c0;
                        o.y = uu.y * hv.y + (1.0f - uu.y) * c1;
                        *(float2*)(out + rb + gc) = o;
                    }
                }
            }
        }

        // ---- publish completion (A tiles) ----
        __threadfence();
        __syncthreads();                 // also protects sm_bcast reuse
        if (region < 3 && tid == 0) atomicAdd(&g_done[mblk], 1u);
    }
}

// ---------------- init: zero scheduling counters ----------------
__global__ void init_counters()
{
    if (threadIdx.x < 64) g_done[threadIdx.x] = 0u;
    if (threadIdx.x == 64) g_work = 0u;
}

// ---------------- fused fp32 -> fp16 conversion ----------------
__global__ void __launch_bounds__(256)
cvt_all_kernel(const float4* __restrict__ x, const float4* __restrict__ h,
               const float4* __restrict__ wi, const float4* __restrict__ wh)
{
    const int nx = BATCH * U2 / 4;    // 4,194,304
    const int nw = U2 * GL / 4;       // 3,145,728
    const int total = 2 * nx + 2 * nw;
    for (int i = blockIdx.x * blockDim.x + threadIdx.x; i < total;
         i += gridDim.x * blockDim.x) {
        const float4* src; __half2* dst; int j;
        if (i < nx)               { src = x;  dst = (__half2*)g_xH;   j = i; }
        else if (i < 2 * nx)      { src = h;  dst = (__half2*)g_hH;   j = i - nx; }
        else if (i < 2 * nx + nw) { src = wi; dst = (__half2*)g_WinH; j = i - 2 * nx; }
        else                      { src = wh; dst = (__half2*)g_WhH;  j = i - 2 * nx - nw; }
        float4 v = src[j];
        dst[2 * j + 0] = __floats2half2_rn(v.x, v.y);
        dst[2 * j + 1] = __floats2half2_rn(v.z, v.w);
    }
}

// ---------------- host ----------------
extern "C" void kernel_launch(void* const* d_in, const int* in_sizes, int n_in,
                              void* d_out, int out_size)
{
    const float* x    = (const float*)d_in[0];
    const float* h    = (const float*)d_in[1];
    const float* Win  = (const float*)d_in[2];
    const float* Wh   = (const float*)d_in[3];
    const float* bias = (const float*)d_in[4];
    float* out = (float*)d_out;

    static int nsm = 0;
    if (nsm == 0) {
        cudaDeviceGetAttribute(&nsm, cudaDevAttrMultiProcessorCount, 0);
        if (nsm <= 0) nsm = 148;
        cudaFuncSetAttribute(gru_fused, cudaFuncAttributeMaxDynamicSharedMemorySize,
                             SMEM_ALLOC);
    }

    init_counters<<<1, 128>>>();
    cvt_all_kernel<<<2048, 256>>>((const float4*)x, (const float4*)h,
                                  (const float4*)Win, (const float4*)Wh);
    gru_fused<<<nsm, THREADS, SMEM_ALLOC>>>(h, bias, out);
}